// round 15
// baseline (speedup 1.0000x reference)
#include <cuda_runtime.h>
#include <cstdint>

// ---------------- problem constants ----------------
#define BATCH   64
#define C1      3
#define L1      8192
#define PAD1    2
#define KW1     80
#define O1      6
#define LCONV1  8117          // 8192 + 4 - 80 + 1
#define LP1     4058          // LCONV1 // 2

#define O2      16
#define C2      6
#define KW2     3
#define LP2     2028

#define NFEAT   32448         // 16 * 2028
#define H1      120
#define H2      84
#define NOUT    10

#define NKSPLIT 312
#define KCHUNK  104           // 32448 / 312 (exact, = 26 float4)

#define QSCALE    4096.0f
#define DEQ_HALF  (0.5f / QSCALE)

// ---------------- scratch (static device globals; no allocs) ----------------
__device__ float g_y1[BATCH * O1 * LP1];            // pooled conv1 out
__device__ __align__(16) float g_y2[BATCH * NFEAT]; // pooled conv2 out
__device__ __align__(16) float g_part[BATCH * H1 * NKSPLIT]; // [b][o][nk]
__device__ float g_h1[BATCH * H1];
__device__ float g_h2[BATCH * H2];

// nop kernel: keep ncu's fixed capture point (launch index 3) on fc1
__global__ void nop_kernel() {}

// =====================================================================
// K1: tropical min-plus conv1 (K=80, pad=2) fused with avgpool(2)
//   s16x2 DPX over PRE-PACKED pairs xp[j] = (x[j], x[j+8]); refill is a
//   single LDS.32. TILE1=1024 + o-split z=3 -> 1536 blocks.
// =====================================================================
#define T1       16
#define NTHR1    128
#define TILE1    1024
#define NTILE1   8            // 8 * 1024 >= 8117
#define XP_N     1104         // TILE1 + KW1
#define XP_COLS  70           // max col 68 (incl refill), +1

__global__ void __launch_bounds__(NTHR1) conv1_kernel(const float* __restrict__ x,
                                                      const float* __restrict__ w1) {
    __shared__ unsigned xp[C1][16][XP_COLS];  // xp[c][j&15][j>>4] = (x[j], x[j+8])
    __shared__ unsigned ws2[O1 * C1 * KW1];   // s16 weight duplicated both halves

    const int b   = blockIdx.y;
    const int t0  = blockIdx.x * TILE1;
    const int oz  = blockIdx.z;               // o in {2*oz, 2*oz+1}
    const int tid = threadIdx.x;

    for (int i = tid; i < C1 * XP_N; i += NTHR1) {
        int c = i / XP_N;
        int j = i - c * XP_N;
        int g0 = t0 + j - PAD1;
        int g1 = g0 + 8;
        const float* xc = &x[(b * C1 + c) * L1];
        float v0 = (g0 >= 0 && g0 < L1) ? xc[g0] : 0.0f;
        float v1 = (g1 >= 0 && g1 < L1) ? xc[g1] : 0.0f;
        unsigned lo = (unsigned short)(short)__float2int_rn(v0 * QSCALE);
        unsigned hi = (unsigned short)(short)__float2int_rn(v1 * QSCALE);
        xp[c][j & 15][j >> 4] = lo | (hi << 16);
    }
    for (int i = tid; i < O1 * C1 * KW1; i += NTHR1) {
        int wq = __float2int_rn(w1[i] * QSCALE);
        ws2[i] = ((unsigned)wq & 0xFFFFu) | ((unsigned)wq << 16);
    }
    __syncthreads();

    const int col  = tid & 63;
    const int half = tid >> 6;
    const int base = col * T1;
    const int o    = oz * 2 + half;

    {
        int isum[T1];
        #pragma unroll 1
        for (int c = 0; c < C1; c++) {
            unsigned acc2[8];
            unsigned win2[8];
            #pragma unroll
            for (int q = 0; q < 8; q++) {
                acc2[q] = 0x7FFF7FFFu;
                win2[q] = xp[c][q][col];
            }
            const unsigned* wp = &ws2[(o * C1 + c) * KW1];
            #pragma unroll 1
            for (int k16 = 0; k16 < KW1 / 16; k16++) {
                #pragma unroll
                for (int kk = 0; kk < 16; kk++) {
                    unsigned w = wp[k16 * 16 + kk];
                    const int h = kk & 7;
                    #pragma unroll
                    for (int q = 0; q < 8; q++)
                        acc2[q] = __viaddmin_s16x2(win2[(h + q) & 7], w, acc2[q]);
                    win2[h] = xp[c][(kk + 8) & 15][col + k16 + ((kk + 8) >> 4)];
                }
            }
            #pragma unroll
            for (int q = 0; q < 8; q++) {
                int lo = (int)(short)(acc2[q] & 0xFFFFu);
                int hi = (int)acc2[q] >> 16;
                if (c == 0) { isum[q] = lo; isum[q + 8] = hi; }
                else        { isum[q] += lo; isum[q + 8] += hi; }
            }
        }
        int tg = t0 + base;
        #pragma unroll
        for (int j2 = 0; j2 < T1 / 2; j2++) {
            int tp = (tg >> 1) + j2;
            if (tp < LP1) {
                float v = (float)(isum[2 * j2] + isum[2 * j2 + 1]) * DEQ_HALF;
                g_y1[(b * O1 + o) * LP1 + tp] = v;
            }
        }
    }
}

// =====================================================================
// K2: tropical max-plus conv2 (K=3) fused with avgpool(2)
// =====================================================================
#define TP2 256

__global__ void __launch_bounds__(256) conv2_kernel(const float* __restrict__ w2) {
    __shared__ float ys[C2][2 * TP2 + 4];
    __shared__ float wsm[O2 * C2 * KW2];

    const int b   = blockIdx.y;
    const int tp0 = blockIdx.x * TP2;
    const int tid = threadIdx.x;

    for (int i = tid; i < O2 * C2 * KW2; i += TP2) wsm[i] = w2[i];

    for (int i = tid; i < C2 * 515; i += 256) {
        int c = i / 515, j = i - c * 515;
        int g = 2 * tp0 + j;
        ys[c][j] = (g < LP1) ? g_y1[(b * C2 + c) * LP1 + g] : 0.0f;
    }
    __syncthreads();

    int tp = tp0 + tid;
    if (tp >= LP2) return;

    float xv[C2][4];
    #pragma unroll
    for (int c = 0; c < C2; c++)
        #pragma unroll
        for (int d = 0; d < 4; d++)
            xv[c][d] = ys[c][2 * tid + d];

    #pragma unroll 1
    for (int o = 0; o < O2; o++) {
        float s0 = 0.0f, s1 = 0.0f;
        #pragma unroll
        for (int c = 0; c < C2; c++) {
            float m0 = -__int_as_float(0x7F800000);
            float m1 = m0;
            #pragma unroll
            for (int kk = 0; kk < KW2; kk++) {
                float w = wsm[(o * C2 + c) * KW2 + kk];
                m0 = fmaxf(m0, xv[c][kk] + w);
                m1 = fmaxf(m1, xv[c][kk + 1] + w);
            }
            s0 += m0;
            s1 += m1;
        }
        g_y2[b * NFEAT + o * LP2 + tp] = (s0 + s1) * 0.5f;
    }
}

// =====================================================================
// K3: fc1 split-K GEMM v3: part[b][o][nk] = sum_{k in chunk} X[b,k]*W[o,k]
//   Single K-tile (KT=KCHUNK=104): ONE sync, float4 staging (~17 LDG.128
//   per thread, deep MLP). grid (312,2)=624 blocks, 192 thr, 4b x 5o.
// =====================================================================
#define OT 60
#define KT 104
#define XS_STRIDE 108         // 16B-aligned rows, bank-phase 12

__global__ void __launch_bounds__(192) fc1_kernel(const float* __restrict__ fc1_w) {
    __shared__ float Xs[64][XS_STRIDE];
    __shared__ float Ws[OT][XS_STRIDE];

    const int nk  = blockIdx.x;
    const int ot  = blockIdx.y;
    const int tid = threadIdx.x;
    const int bq  = tid / 12;     // 0..15 -> 4 batches each
    const int oq  = tid % 12;     // 0..11 -> 5 outputs each
    const int k0  = nk * KCHUNK;  // multiple of 4 -> float4-aligned

    // stage X: 64 rows x 26 float4
    for (int f = tid; f < 64 * 26; f += 192) {
        int row = f / 26, c4 = f - row * 26;
        float4 v = *(const float4*)&g_y2[row * NFEAT + k0 + c4 * 4];
        *(float4*)&Xs[row][c4 * 4] = v;
    }
    // stage W: 60 rows x 26 float4
    for (int f = tid; f < OT * 26; f += 192) {
        int row = f / 26, c4 = f - row * 26;
        float4 v = *(const float4*)&fc1_w[(ot * OT + row) * NFEAT + k0 + c4 * 4];
        *(float4*)&Ws[row][c4 * 4] = v;
    }
    __syncthreads();

    float acc[4][5] = {};
    #pragma unroll 4
    for (int kk = 0; kk < KT; kk++) {
        float xv[4], wv[5];
        #pragma unroll
        for (int i = 0; i < 4; i++) xv[i] = Xs[bq * 4 + i][kk];
        #pragma unroll
        for (int j = 0; j < 5; j++) wv[j] = Ws[oq * 5 + j][kk];
        #pragma unroll
        for (int i = 0; i < 4; i++)
            #pragma unroll
            for (int j = 0; j < 5; j++)
                acc[i][j] += xv[i] * wv[j];
    }

    #pragma unroll
    for (int i = 0; i < 4; i++)
        #pragma unroll
        for (int j = 0; j < 5; j++) {
            int b = bq * 4 + i, o = ot * OT + oq * 5 + j;
            g_part[(b * H1 + o) * NKSPLIT + nk] = acc[i][j];
        }
}

// =====================================================================
// K4a: h1 reduce (+bias+relu); K4b: fc2; K4c: fc3
// =====================================================================
__global__ void __launch_bounds__(256) h1_kernel(const float* __restrict__ fc1_b) {
    int idx = blockIdx.x * 256 + threadIdx.x;
    if (idx >= BATCH * H1) return;
    int o = idx % H1;
    const float4* p4 = (const float4*)&g_part[idx * NKSPLIT];
    float s0 = 0.0f, s1 = 0.0f;
    #pragma unroll
    for (int q = 0; q < NKSPLIT / 4; q += 2) {     // 78 float4, 2 at a time
        float4 a = p4[q + 0], b4 = p4[q + 1];
        s0 += (a.x + a.y) + (a.z + a.w);
        s1 += (b4.x + b4.y) + (b4.z + b4.w);
    }
    g_h1[idx] = fmaxf(s0 + s1 + fc1_b[o], 0.0f);
}

__global__ void __launch_bounds__(256) h2_kernel(const float* __restrict__ fc2_w,
                                                 const float* __restrict__ fc2_b) {
    int gw   = blockIdx.x * 8 + (threadIdx.x >> 5);
    int lane = threadIdx.x & 31;
    if (gw >= BATCH * H2) return;
    int b = gw / H2, o = gw - b * H2;
    float s = 0.0f;
    #pragma unroll
    for (int r = 0; r < 4; r++) {
        int k = lane + 32 * r;
        if (k < H1) s += fc2_w[o * H1 + k] * g_h1[b * H1 + k];
    }
    #pragma unroll
    for (int d = 16; d > 0; d >>= 1) s += __shfl_xor_sync(0xFFFFFFFFu, s, d);
    if (lane == 0) g_h2[gw] = fmaxf(s + fc2_b[o], 0.0f);
}

__global__ void __launch_bounds__(256) out_kernel(const float* __restrict__ fc3_w,
                                                  const float* __restrict__ fc3_b,
                                                  float* __restrict__ out) {
    int gw   = blockIdx.x * 8 + (threadIdx.x >> 5);
    int lane = threadIdx.x & 31;
    if (gw >= BATCH * NOUT) return;
    int b = gw / NOUT, o = gw - b * NOUT;
    float s = 0.0f;
    #pragma unroll
    for (int r = 0; r < 3; r++) {
        int k = lane + 32 * r;
        if (k < H2) s += fc3_w[o * H2 + k] * g_h2[b * H2 + k];
    }
    #pragma unroll
    for (int d = 16; d > 0; d >>= 1) s += __shfl_xor_sync(0xFFFFFFFFu, s, d);
    if (lane == 0) out[gw] = s + fc3_b[o];
}

// ---------------- launch: identify inputs by UNIQUE element counts ----------
extern "C" void kernel_launch(void* const* d_in, const int* in_sizes, int n_in,
                              void* d_out, int out_size) {
    const float* x     = nullptr;
    const float* w1    = nullptr;
    const float* w2    = nullptr;
    const float* fc1_w = nullptr;
    const float* fc1_b = nullptr;
    const float* fc2_w = nullptr;
    const float* fc2_b = nullptr;
    const float* fc3_w = nullptr;
    const float* fc3_b = nullptr;

    for (int i = 0; i < n_in; i++) {
        const float* p = (const float*)d_in[i];
        switch (in_sizes[i]) {
            case BATCH * C1 * L1:   x     = p; break;
            case O1 * C1 * KW1:     w1    = p; break;
            case O2 * C2 * KW2:     w2    = p; break;
            case H1 * NFEAT:        fc1_w = p; break;
            case H1:                fc1_b = p; break;
            case H2 * H1:           fc2_w = p; break;
            case H2:                fc2_b = p; break;
            case NOUT * H2:         fc3_w = p; break;
            case NOUT:              fc3_b = p; break;
            default: break;
        }
    }

    // 1 nop so ncu's fixed capture point (launch index 3) stays on fc1
    nop_kernel<<<1, 32>>>();
    conv1_kernel<<<dim3(NTILE1, BATCH, 3), NTHR1>>>(x, w1);
    conv2_kernel<<<dim3(8, BATCH), 256>>>(w2);
    fc1_kernel<<<dim3(NKSPLIT, 2), 192>>>(fc1_w);
    h1_kernel<<<(BATCH * H1 + 255) / 256, 256>>>(fc1_b);
    h2_kernel<<<(BATCH * H2 + 7) / 8, 256>>>(fc2_w, fc2_b);
    out_kernel<<<(BATCH * NOUT + 7) / 8, 256>>>(fc3_w, fc3_b, (float*)d_out);
}